// round 1
// baseline (speedup 1.0000x reference)
#include <cuda_runtime.h>
#include <cuda_bf16.h>

#define NEGV (-10000.0f)
#define W 2048
#define H 2048
#define ROWS_PER_BLOCK 64
#define TPB 256

// Horizontal 5-tap max for 4 consecutive outputs starting at col0 (col0 % 4 == 0).
// Needs cols [col0-2, col0+5]: float2 left halo + float4 center + float2 right halo.
__device__ __forceinline__ float4 hrow_max(const float* __restrict__ plane, int y, int col0) {
    if ((unsigned)y >= (unsigned)H) {
        return make_float4(NEGV, NEGV, NEGV, NEGV);
    }
    const float* row = plane + (size_t)y * W;

    float4 c = *reinterpret_cast<const float4*>(row + col0);
    float2 l, r;
    if (col0 > 0) {
        l = *reinterpret_cast<const float2*>(row + col0 - 2);   // 8B aligned (col0-2 even)
    } else {
        l = make_float2(NEGV, NEGV);
    }
    if (col0 + 4 < W) {
        r = *reinterpret_cast<const float2*>(row + col0 + 4);   // 8B aligned
    } else {
        r = make_float2(NEGV, NEGV);
    }

    // f[0..7] = cols col0-2 .. col0+5
    float f0 = l.x, f1 = l.y, f2 = c.x, f3 = c.y, f4 = c.z, f5 = c.w, f6 = r.x, f7 = r.y;

    // pairwise maxes, then window-5 = max(pair[j], pair[j+2], f[j+4])
    float p0 = fmaxf(f0, f1);
    float p1 = fmaxf(f1, f2);
    float p2 = fmaxf(f2, f3);
    float p3 = fmaxf(f3, f4);
    float p4 = fmaxf(f4, f5);
    float p5 = fmaxf(f5, f6);

    float4 h;
    h.x = fmaxf(fmaxf(p0, p2), f4);
    h.y = fmaxf(fmaxf(p1, p3), f5);
    h.z = fmaxf(fmaxf(p2, p4), f6);
    h.w = fmaxf(fmaxf(p3, p5), f7);
    return h;
}

__device__ __forceinline__ float4 max4(float4 a, float4 b) {
    return make_float4(fmaxf(a.x, b.x), fmaxf(a.y, b.y), fmaxf(a.z, b.z), fmaxf(a.w, b.w));
}

__global__ __launch_bounds__(TPB)
void dilation5x5_kernel(const float* __restrict__ in, float* __restrict__ out) {
    const int col0 = 4 * (blockIdx.x * TPB + threadIdx.x);
    const size_t plane_off = (size_t)blockIdx.z * (size_t)H * (size_t)W;
    const float* __restrict__ pin  = in  + plane_off;
    float* __restrict__ pout = out + plane_off;

    const int y0 = blockIdx.y * ROWS_PER_BLOCK;

    // Prime ring buffer with rows y0-2 .. y0+1
    float4 h0 = hrow_max(pin, y0 - 2, col0);
    float4 h1 = hrow_max(pin, y0 - 1, col0);
    float4 h2 = hrow_max(pin, y0    , col0);
    float4 h3 = hrow_max(pin, y0 + 1, col0);

    #pragma unroll 4
    for (int y = y0; y < y0 + ROWS_PER_BLOCK; ++y) {
        float4 h4 = hrow_max(pin, y + 2, col0);

        float4 o = max4(max4(max4(h0, h1), max4(h2, h3)), h4);
        *reinterpret_cast<float4*>(pout + (size_t)y * W + col0) = o;

        h0 = h1; h1 = h2; h2 = h3; h3 = h4;
    }
}

extern "C" void kernel_launch(void* const* d_in, const int* in_sizes, int n_in,
                              void* d_out, int out_size) {
    const float* image = (const float*)d_in[0];
    // d_in[1] is the 5x5 all-ones structuring element: neigh offsets are all 0,
    // so the op is exactly a 5x5 sliding max (pad -10000 never wins vs interior >= 0).
    float* out = (float*)d_out;

    dim3 block(TPB, 1, 1);
    dim3 grid(W / (4 * TPB), H / ROWS_PER_BLOCK, 24);  // 2 x 32 x 24
    dilation5x5_kernel<<<grid, block>>>(image, out);
}

// round 2
// speedup vs baseline: 1.1831x; 1.1831x over previous
#include <cuda_runtime.h>
#include <cuda_bf16.h>

#define NEGV (-10000.0f)
#define W 2048
#define H 2048
#define RPB 128
#define TPB 256

__device__ __forceinline__ float4 max4(float4 a, float4 b) {
    return make_float4(fmaxf(a.x, b.x), fmaxf(a.y, b.y), fmaxf(a.z, b.z), fmaxf(a.w, b.w));
}

// Horizontal 5-tap max over cols [col0-2, col0+5] -> 4 outputs.
__device__ __forceinline__ float4 hmax(float2 l, float4 c, float2 r) {
    float f0 = l.x, f1 = l.y, f2 = c.x, f3 = c.y, f4 = c.z, f5 = c.w, f6 = r.x, f7 = r.y;
    float p0 = fmaxf(f0, f1);
    float p1 = fmaxf(f1, f2);
    float p2 = fmaxf(f2, f3);
    float p3 = fmaxf(f3, f4);
    float p4 = fmaxf(f4, f5);
    float p5 = fmaxf(f5, f6);
    return make_float4(fmaxf(fmaxf(p0, p2), f4),
                       fmaxf(fmaxf(p1, p3), f5),
                       fmaxf(fmaxf(p2, p4), f6),
                       fmaxf(fmaxf(p3, p5), f7));
}

// Unconditional, always-in-bounds loads; edge patch via FSEL only.
__device__ __forceinline__ float4 loadrow(const float* __restrict__ rp,
                                          int loff, int roff, bool hl, bool hr) {
    float4 c = *reinterpret_cast<const float4*>(rp);
    float2 l = *reinterpret_cast<const float2*>(rp + loff);
    float2 r = *reinterpret_cast<const float2*>(rp + roff);
    if (!hl) { l.x = NEGV; l.y = NEGV; }
    if (!hr) { r.x = NEGV; r.y = NEGV; }
    return hmax(l, c, r);
}

template <bool CT, bool CB>
__device__ __forceinline__ void strip(const float* __restrict__ pin,
                                      float* __restrict__ pout,
                                      int y0, int col0) {
    const bool hl = col0 > 0;
    const bool hr = col0 + 4 < W;
    const int loff = hl ? -2 : 0;   // clamped: still in-bounds when at the edge
    const int roff = hr ? 4 : 0;

    const float* p  = pin  + (size_t)y0 * W + col0;
    float*       po = pout + (size_t)y0 * W + col0;

    float4 h0, h1, h2, h3;
    if (CT) {
        h0 = make_float4(NEGV, NEGV, NEGV, NEGV);
        h1 = h0;
    } else {
        h0 = loadrow(p - 2 * W, loff, roff, hl, hr);
        h1 = loadrow(p - 1 * W, loff, roff, hl, hr);
    }
    h2 = loadrow(p,     loff, roff, hl, hr);
    h3 = loadrow(p + W, loff, roff, hl, hr);

    const float* pl = p + 2 * W;          // row y0+2 = first h4 row
    const int n = CB ? (RPB - 2) : RPB;

    #pragma unroll 8
    for (int i = 0; i < n; ++i) {
        float4 h4 = loadrow(pl, loff, roff, hl, hr);
        pl += W;
        float4 o = max4(max4(max4(h0, h1), max4(h2, h3)), h4);
        __stcs(reinterpret_cast<float4*>(po), o);
        po += W;
        h0 = h1; h1 = h2; h2 = h3; h3 = h4;
    }
    if (CB) {
        // rows H-2 and H-1: the h4 rows (H, H+1) are OOB -> NEGV, never win.
        float4 o = max4(max4(h0, h1), max4(h2, h3));
        __stcs(reinterpret_cast<float4*>(po), o);
        po += W;
        o = max4(max4(h1, h2), h3);
        __stcs(reinterpret_cast<float4*>(po), o);
    }
}

__global__ __launch_bounds__(TPB)
void dilation5x5_kernel(const float* __restrict__ in, float* __restrict__ out) {
    const int col0 = 4 * (blockIdx.x * TPB + threadIdx.x);
    const size_t plane_off = (size_t)blockIdx.z * (size_t)H * (size_t)W;
    const int y0 = blockIdx.y * RPB;

    const float* __restrict__ pin  = in  + plane_off;
    float* __restrict__       pout = out + plane_off;

    if (blockIdx.y == 0)
        strip<true, false>(pin, pout, y0, col0);
    else if (blockIdx.y == gridDim.y - 1)
        strip<false, true>(pin, pout, y0, col0);
    else
        strip<false, false>(pin, pout, y0, col0);
}

extern "C" void kernel_launch(void* const* d_in, const int* in_sizes, int n_in,
                              void* d_out, int out_size) {
    const float* image = (const float*)d_in[0];
    // d_in[1] is the all-ones 5x5 SE: neigh offsets are 0, so this is exactly a
    // 5x5 sliding max with -1e4 padding (pad never beats interior values >= 0).
    float* out = (float*)d_out;

    dim3 block(TPB, 1, 1);
    dim3 grid(W / (4 * TPB), H / RPB, 24);  // 2 x 16 x 24 = 768 blocks
    dilation5x5_kernel<<<grid, block>>>(image, out);
}